// round 4
// baseline (speedup 1.0000x reference)
#include <cuda_runtime.h>

// RandomShiftsAug on GB300 — integer-shift copy with edge clamp.
// out[n,c,y,x] = in[n,c, clamp(y+sy-4,0,127), clamp(x+sx-4,0,127)]
// R3: aligned LDG.128-only read path + warp-uniform quad select (sx is
// uniform per warp since a warp covers one full row of one (n,c,y)).

#define PADV 4
#define CB   9
#define HB   128
#define TOTAL4 18874368   // 512*9*128*32 float4s

__global__ void __launch_bounds__(256)
random_shift_copy_kernel(const float* __restrict__ x,
                         const int* __restrict__ shift,
                         float* __restrict__ out)
{
    int idx4 = blockIdx.x * blockDim.x + threadIdx.x;
    if (idx4 >= TOTAL4) return;

    int xq = (idx4 & 31) << 2;   // output start column (0..124)
    int t  = idx4 >> 5;
    int y  = t & (HB - 1);
    int nc = t >> 7;             // n*9 + c
    int n  = nc / CB;

    int sx = shift[2 * n]     - PADV;   // warp-uniform
    int sy = shift[2 * n + 1] - PADV;

    int ys = y + sy;
    ys = ys < 0 ? 0 : (ys > HB - 1 ? HB - 1 : ys);

    const float4* __restrict__ row4 =
        reinterpret_cast<const float4*>(x) + ((long long)nc * HB + ys) * (HB / 4);
    const float* __restrict__ row = reinterpret_cast<const float*>(row4);

    int c0 = xq + sx;            // first needed source column (may be <0 or >124)
    int qa = c0 >> 2;            // arithmetic shift = floor divide (c0 >= -4)
    int r  = c0 & 3;             // warp-uniform rotation
    int qac = qa < 0 ? 0 : (qa > 31 ? 31 : qa);
    int qbc = qa + 1 > 31 ? 31 : qa + 1;   // qa+1 >= 0 always

    float4 A = __ldcs(row4 + qac);
    float4 B = __ldcs(row4 + qbc);

    // Edge-clamp values, loaded only in lanes that need them (predicated LDG).
    float first = 0.f, last = 0.f;
    if (c0 < 0)           first = __ldg(row);           // row[0]
    if (c0 + 3 > HB - 1)  last  = __ldg(row + HB - 1);  // row[127]

    float o0, o1, o2, o3;
    switch (r) {                 // warp-uniform branch
        case 0:  o0 = A.x; o1 = A.y; o2 = A.z; o3 = A.w; break;
        case 1:  o0 = A.y; o1 = A.z; o2 = A.w; o3 = B.x; break;
        case 2:  o0 = A.z; o1 = A.w; o2 = B.x; o3 = B.y; break;
        default: o0 = A.w; o1 = B.x; o2 = B.y; o3 = B.z; break;
    }

    // Per-component edge fixes (only lanes 0/31 can trigger; sx in [-4,4]).
    if (c0     < 0) o0 = first; else if (c0     > HB - 1) o0 = last;
    if (c0 + 1 < 0) o1 = first; else if (c0 + 1 > HB - 1) o1 = last;
    if (c0 + 2 < 0) o2 = first; else if (c0 + 2 > HB - 1) o2 = last;
    if (c0 + 3 < 0) o3 = first; else if (c0 + 3 > HB - 1) o3 = last;

    float4 v; v.x = o0; v.y = o1; v.z = o2; v.w = o3;
    __stcs(reinterpret_cast<float4*>(out) + idx4, v);
}

extern "C" void kernel_launch(void* const* d_in, const int* in_sizes, int n_in,
                              void* d_out, int out_size)
{
    const float* x     = (const float*)d_in[0];
    const int*   shift = (const int*)d_in[1];
    float*       out   = (float*)d_out;

    const int threads = 256;
    const int blocks  = (TOTAL4 + threads - 1) / threads;  // 73728
    random_shift_copy_kernel<<<blocks, threads>>>(x, shift, out);
}

// round 6
// speedup vs baseline: 1.1642x; 1.1642x over previous
#include <cuda_runtime.h>

// RandomShiftsAug on GB300 — integer-shift copy with edge clamp.
// out[n,c,y,x] = in[n,c, clamp(y+sy-4,0,127), clamp(x+sx-4,0,127)]
//
// R5: shared-memory staging. CTA = 8 rows of one (n,c) image.
//  load : warp w stages source row clamp(y0+w+sy) with aligned LDG.128
//         (one contiguous 512B segment per warp).
//  store: thread (w,l) writes output cols {l, l+32, l+64, l+96} of row y0+w;
//         smem reads are stride-1 (conflict-free), STG.32 fully coalesced.
// Both HBM streams are aligned and exactly-sized -> pure copy roofline.

#define PADV 4
#define CB   9
#define HB   128

__global__ void __launch_bounds__(256)
random_shift_smem_kernel(const float* __restrict__ x,
                         const int* __restrict__ shift,
                         float* __restrict__ out)
{
    __shared__ float srow[8][HB];

    int cta = blockIdx.x;          // 73728 CTAs
    int nc  = cta >> 4;            // (n*9 + c)
    int y0  = (cta & 15) << 3;     // first of 8 output rows
    int n   = nc / CB;

    int sx = shift[2 * n]     - PADV;
    int sy = shift[2 * n + 1] - PADV;

    int w = threadIdx.x >> 5;      // warp = row within octet
    int l = threadIdx.x & 31;      // lane

    // ---- stage source rows (aligned LDG.128, 512B contiguous per warp) ----
    int ys = y0 + w + sy;
    ys = ys < 0 ? 0 : (ys > HB - 1 ? HB - 1 : ys);
    const float4* __restrict__ src4 =
        reinterpret_cast<const float4*>(x) + ((long long)nc * HB + ys) * (HB / 4);
    reinterpret_cast<float4*>(srow[w])[l] = __ldcs(src4 + l);

    __syncthreads();

    // ---- emit shifted row (conflict-free LDS, coalesced STG.32) ----
    float* __restrict__ dst = out + ((long long)nc * HB + (y0 + w)) * HB;

    #pragma unroll
    for (int m = 0; m < 4; m++) {
        int col = l + (m << 5);
        int sc  = col + sx;
        sc = sc < 0 ? 0 : (sc > HB - 1 ? HB - 1 : sc);
        __stcs(dst + col, srow[w][sc]);
    }
}

extern "C" void kernel_launch(void* const* d_in, const int* in_sizes, int n_in,
                              void* d_out, int out_size)
{
    const float* x     = (const float*)d_in[0];
    const int*   shift = (const int*)d_in[1];
    float*       out   = (float*)d_out;

    // 512*9 images * 16 row-octets = 73728 CTAs
    random_shift_smem_kernel<<<512 * CB * 16, 256>>>(x, shift, out);
}

// round 9
// speedup vs baseline: 1.2646x; 1.0862x over previous
#include <cuda_runtime.h>

// RandomShiftsAug on GB300 — integer-shift copy with edge clamp.
// out[n,c,y,x] = in[n,c, clamp(y+sy-4,0,127), clamp(x+sx-4,0,127)]
//
// R7: warp-autonomous smem staging, no CTA barrier.
//  Each warp owns 4 rows of one (n,c) image:
//   load : 4 independent aligned LDG.128 per thread (MLP=4), one per row.
//   sync : __syncwarp only (row exchange is intra-warp).
//   store: per row, 4 coalesced STG.32 from stride-1 (conflict-free) smem.

#define PADV 4
#define CB   9
#define HB   128
#define RW   4            // rows per warp

__global__ void __launch_bounds__(256)
random_shift_warp_kernel(const float* __restrict__ x,
                         const int* __restrict__ shift,
                         float* __restrict__ out)
{
    __shared__ float srow[8][RW][HB];

    int w = threadIdx.x >> 5;
    int l = threadIdx.x & 31;

    int gwarp = blockIdx.x * 8 + w;    // 147456 warps total
    int grp   = gwarp & 31;            // 32 row-quartets per image
    int nc    = gwarp >> 5;            // n*9 + c
    int y0    = grp << 2;
    int n     = nc / CB;

    int sx = shift[2 * n]     - PADV;  // warp-uniform
    int sy = shift[2 * n + 1] - PADV;

    const float4* __restrict__ img4 =
        reinterpret_cast<const float4*>(x) + (long long)nc * (HB * HB / 4);

    // ---- stage 4 source rows, 4 LDGs in flight per thread ----
    #pragma unroll
    for (int r = 0; r < RW; r++) {
        int ys = y0 + r + sy;
        ys = ys < 0 ? 0 : (ys > HB - 1 ? HB - 1 : ys);
        reinterpret_cast<float4*>(srow[w][r])[l] = __ldcs(img4 + ys * (HB / 4) + l);
    }

    __syncwarp();

    // ---- emit 4 shifted rows ----
    float* __restrict__ dst0 = out + ((long long)nc * HB + y0) * HB;

    #pragma unroll
    for (int r = 0; r < RW; r++) {
        float* __restrict__ dst = dst0 + r * HB;
        #pragma unroll
        for (int m = 0; m < 4; m++) {
            int col = l + (m << 5);
            int sc  = col + sx;
            sc = sc < 0 ? 0 : (sc > HB - 1 ? HB - 1 : sc);
            __stcs(dst + col, srow[w][r][sc]);
        }
    }
}

extern "C" void kernel_launch(void* const* d_in, const int* in_sizes, int n_in,
                              void* d_out, int out_size)
{
    const float* x     = (const float*)d_in[0];
    const int*   shift = (const int*)d_in[1];
    float*       out   = (float*)d_out;

    // 512*9 images * 32 row-quartets = 147456 warps / 8 per CTA = 18432 CTAs
    random_shift_warp_kernel<<<18432, 256>>>(x, shift, out);
}